// round 14
// baseline (speedup 1.0000x reference)
#include <cuda_runtime.h>
#include <cstdint>

// Problem: B=32, N=8192, DIM=256, M=1228
//   in0: x            [B, N, DIM] float32
//   in1: mask_indices [B, M]      int32
//   in2: emb_mask     [1, DIM]    float32
// out: masked_x [B*N*DIM] floats (+ mask_indices as floats if room).

#define DIM      256
#define N_FIX    8192
#define ROWS_PB  64     // rows per block; 64 flags = 2 uint32
#define THREADS  256
#define UNROLL   4      // 4 x 32B in flight per thread = 128B (32 staging regs)

struct __align__(32) f8 { float v[8]; };

// 256-bit global load, streaming (evict-first)
__device__ __forceinline__ f8 ldg256_cs(const float* p) {
    f8 r;
    asm volatile("ld.global.cs.v8.f32 {%0,%1,%2,%3,%4,%5,%6,%7}, [%8];"
                 : "=f"(r.v[0]), "=f"(r.v[1]), "=f"(r.v[2]), "=f"(r.v[3]),
                   "=f"(r.v[4]), "=f"(r.v[5]), "=f"(r.v[6]), "=f"(r.v[7])
                 : "l"(p));
    return r;
}

// 256-bit global store, streaming
__device__ __forceinline__ void stg256_cs(float* p, const f8& r) {
    asm volatile("st.global.cs.v8.f32 [%0], {%1,%2,%3,%4,%5,%6,%7,%8};"
                 :: "l"(p),
                    "f"(r.v[0]), "f"(r.v[1]), "f"(r.v[2]), "f"(r.v[3]),
                    "f"(r.v[4]), "f"(r.v[5]), "f"(r.v[6]), "f"(r.v[7])
                 : "memory");
}

__global__ void __launch_bounds__(THREADS)
fused_mask_kernel(const float* __restrict__ x,
                  const int*   __restrict__ mask_indices,
                  const float* __restrict__ emb_mask,
                  float*       __restrict__ out,
                  float*       __restrict__ out_idx,   // may be null
                  int M, int blocks_per_batch)
{
    __shared__ uint32_t fl[ROWS_PB / 32];   // 2 words

    const int tid = threadIdx.x;
    const int b   = blockIdx.x / blocks_per_batch;
    const int blk = blockIdx.x % blocks_per_batch;
    const int r0  = blk * ROWS_PB;

    if (tid < ROWS_PB / 32) fl[tid] = 0;
    __syncthreads();

    // Vectorized scan of this batch's indices (int4 = 4 indices per load).
    const int* idx_row = mask_indices + (size_t)b * M;
    const int M4 = M >> 2;                       // 307 for M=1228
    const int4* idx4 = reinterpret_cast<const int4*>(idx_row);
    const bool emit = (blk == 0) && (out_idx != nullptr);

    for (int i = tid; i < M4; i += THREADS) {
        int4 q = __ldg(&idx4[i]);
        int l0 = q.x - r0, l1 = q.y - r0, l2 = q.z - r0, l3 = q.w - r0;
        if ((unsigned)l0 < (unsigned)ROWS_PB) atomicOr(&fl[l0 >> 5], 1u << (l0 & 31));
        if ((unsigned)l1 < (unsigned)ROWS_PB) atomicOr(&fl[l1 >> 5], 1u << (l1 & 31));
        if ((unsigned)l2 < (unsigned)ROWS_PB) atomicOr(&fl[l2 >> 5], 1u << (l2 & 31));
        if ((unsigned)l3 < (unsigned)ROWS_PB) atomicOr(&fl[l3 >> 5], 1u << (l3 & 31));
        if (emit) {
            float4 f = make_float4((float)q.x, (float)q.y, (float)q.z, (float)q.w);
            reinterpret_cast<float4*>(out_idx + (size_t)b * M)[i] = f;
        }
    }
    // remainder (M % 4) — none for M=1228, but stay general
    for (int i = (M4 << 2) + tid; i < M; i += THREADS) {
        int idx = idx_row[i];
        int local = idx - r0;
        if ((unsigned)local < (unsigned)ROWS_PB)
            atomicOr(&fl[local >> 5], 1u << (local & 31));
        if (emit) out_idx[(size_t)b * M + i] = (float)idx;
    }
    __syncthreads();

    // bitmask into registers (broadcast LDS, conflict-free)
    uint32_t fw[ROWS_PB / 32];
    #pragma unroll
    for (int w = 0; w < ROWS_PB / 32; ++w) fw[w] = fl[w];

    // 32 threads per row (32 x 32B = 1KB row), 8 rows in parallel per block
    const int sub  = tid >> 5;        // 0..7: row lane within a group of 8 rows
    const int col8 = tid & 31;        // 32B lane within row

    const f8 emb = ldg256_cs(emb_mask + col8 * 8);

    const size_t baseF = ((size_t)b * N_FIX + r0) * DIM;   // float offset
    const float* __restrict__ srcF = x   + baseF;
    float*       __restrict__ dstF = out + baseF;

    // 8 row-iterations per warp-group; UNROLL-wide batches (4 rows in flight)
    #pragma unroll
    for (int it = 0; it < ROWS_PB / 8; it += UNROLL) {
        f8 v[UNROLL];
        #pragma unroll
        for (int u = 0; u < UNROLL; ++u) {
            const int row = (it + u) * 8 + sub;
            const size_t offF = (size_t)row * DIM + col8 * 8;
            const bool masked = (fw[row >> 5] >> (row & 31)) & 1u;
            v[u] = masked ? emb : ldg256_cs(srcF + offF);
        }
        #pragma unroll
        for (int u = 0; u < UNROLL; ++u) {
            const int row = (it + u) * 8 + sub;
            const size_t offF = (size_t)row * DIM + col8 * 8;
            stg256_cs(dstF + offF, v[u]);
        }
    }
}

extern "C" void kernel_launch(void* const* d_in, const int* in_sizes, int n_in,
                              void* d_out, int out_size)
{
    const float* x            = (const float*)d_in[0];
    const int*   mask_indices = (const int*)d_in[1];
    const float* emb_mask     = (const float*)d_in[2];
    float*       out          = (float*)d_out;

    const int x_elems   = in_sizes[0];          // B*N*DIM
    const int idx_elems = in_sizes[1];          // B*M
    const int BN        = x_elems / DIM;        // B*N
    const int B         = BN / N_FIX;
    const int M         = idx_elems / B;

    float* out_idx = (out_size >= x_elems + idx_elems)
                   ? (out + x_elems) : nullptr;

    const int blocks_per_batch = N_FIX / ROWS_PB;   // 128
    fused_mask_kernel<<<B * blocks_per_batch, THREADS>>>(
        x, mask_indices, emb_mask, out, out_idx, M, blocks_per_batch);
}